// round 16
// baseline (speedup 1.0000x reference)
#include <cuda_runtime.h>
#include <cuda_fp16.h>

// Problem constants
#define D 128
#define NMAX 50000
#define EMAX 1600000
#define SCAN_TILE 1024
#define MAX_BLOCKS 64

#if defined(__CUDA_ARCH__) && (__CUDA_ARCH__ >= 900)
#define GRID_DEP_SYNC() cudaGridDependencySynchronize()
#else
#define GRID_DEP_SYNC()
#endif

// Scratch (uint4 => 16B alignment)
__device__ uint4  g_H[NMAX * 16];    // pre-scaled linear output, fp16
__device__ uint4  g_B2[NMAX * 16];   // activations, fp16
__device__ int    g_cnt[NMAX];
__device__ int    g_rowptr[NMAX + 1];
__device__ int    g_cursor[NMAX];
__device__ int    g_adj[EMAX];
__device__ int    g_blk_agg[MAX_BLOCKS];
__device__ int    g_blk_flag[MAX_BLOCKS];
__device__ int    g_is64;

// ---------------------------------------------------------------------------
// Fused: zero cnt + scan flags; block 0 also detects edge dtype.
__global__ void k_init(const unsigned int* __restrict__ p, int* flag,
                       int* cnt, int* blk_flag, int n) {
    int i = blockIdx.x * blockDim.x + threadIdx.x;
    if (i < n) cnt[i] = 0;
    if (i < MAX_BLOCKS) blk_flag[i] = 0;
    if (blockIdx.x == 0) {
        __shared__ unsigned int s;
        if (threadIdx.x == 0) s = 0u;
        __syncthreads();
        unsigned int v = p[threadIdx.x * 2 + 1];
        #pragma unroll
        for (int o = 16; o >= 1; o >>= 1) v |= __shfl_xor_sync(0xffffffffu, v, o);
        if ((threadIdx.x & 31) == 0) atomicOr(&s, v);
        __syncthreads();
        if (threadIdx.x == 0) *flag = (s == 0u) ? 1 : 0;
    }
}

// Count incoming edges, 4 edges/thread vectorized.
__global__ void k_count(const void* __restrict__ ei, const int* __restrict__ flag,
                        int* cnt, int e) {
    int i = (blockIdx.x * blockDim.x + threadIdx.x) * 4;
    if (i >= e) return;
    int e4 = e & ~3;
    if (*flag) {
        const long long* base = (const long long*)ei + e;
        if (i < e4 && (e & 1) == 0) {
            const longlong2* p = (const longlong2*)base;
            longlong2 a = p[i >> 1];
            longlong2 b = p[(i >> 1) + 1];
            atomicAdd(&cnt[(int)a.x], 1);
            atomicAdd(&cnt[(int)a.y], 1);
            atomicAdd(&cnt[(int)b.x], 1);
            atomicAdd(&cnt[(int)b.y], 1);
        } else {
            for (int j = i; j < e && j < i + 4; j++)
                atomicAdd(&cnt[(int)base[j]], 1);
        }
        if (i == 0) {
            for (int j = e4; j < e; j++) atomicAdd(&cnt[(int)base[j]], 1);
        }
    } else {
        const int* base = (const int*)ei + e;
        if (i < e4 && (e & 3) == 0) {
            int4 d = ((const int4*)base)[i >> 2];
            atomicAdd(&cnt[d.x], 1);
            atomicAdd(&cnt[d.y], 1);
            atomicAdd(&cnt[d.z], 1);
            atomicAdd(&cnt[d.w], 1);
        } else {
            for (int j = i; j < e && j < i + 4; j++)
                atomicAdd(&cnt[base[j]], 1);
        }
    }
}

// ---------------------------------------------------------------------------
// Single-kernel exclusive scan, parallel decoupled lookback.
__global__ void k_scan(const int* __restrict__ cnt, int* __restrict__ row_ptr,
                       int* __restrict__ cursor, int* __restrict__ blk_agg,
                       int* blk_flag, int n) {
    __shared__ int ws[8];
    __shared__ int s_prev;
    __shared__ int s_agg;
    const int lane = threadIdx.x & 31, wid = threadIdx.x >> 5;
    if (threadIdx.x == 0) s_prev = 0;
    int i0 = blockIdx.x * SCAN_TILE + threadIdx.x * 4;
    int v[4], s = 0;
    #pragma unroll
    for (int j = 0; j < 4; j++) {
        int i = i0 + j;
        v[j] = (i < n) ? cnt[i] : 0;
        s += v[j];
    }
    int x = s;
    #pragma unroll
    for (int o = 1; o < 32; o <<= 1) {
        int y = __shfl_up_sync(0xffffffffu, x, o);
        if (lane >= o) x += y;
    }
    if (lane == 31) ws[wid] = x;
    __syncthreads();

    if (threadIdx.x == 0) {
        int agg = 0;
        #pragma unroll
        for (int j = 0; j < 8; j++) agg += ws[j];
        s_agg = agg;
        blk_agg[blockIdx.x] = agg;
        __threadfence();
        ((volatile int*)blk_flag)[blockIdx.x] = 1;
    }
    if (threadIdx.x < 64) {
        int partial = 0;
        for (int b = threadIdx.x; b < (int)blockIdx.x; b += 64) {
            while (((volatile int*)blk_flag)[b] == 0) { }
            partial += ((volatile int*)blk_agg)[b];
        }
        if (partial) atomicAdd(&s_prev, partial);
    }
    __syncthreads();

    if (threadIdx.x == 0 && blockIdx.x == gridDim.x - 1)
        row_ptr[n] = s_prev + s_agg;

    int warp_off = 0;
    #pragma unroll
    for (int j = 0; j < 7; j++) if (j < wid) warp_off += ws[j];
    int run = s_prev + warp_off + x - s;
    #pragma unroll
    for (int j = 0; j < 4; j++) {
        int i = i0 + j;
        if (i < n) {
            row_ptr[i] = run;
            cursor[i]  = run;
            run += v[j];
        }
    }
}

// Bin edges into CSR, 4 edges/thread vectorized.
__global__ void k_fill(const void* __restrict__ ei, const int* __restrict__ flag,
                       int* cursor, int* __restrict__ adj, int e) {
    int i = (blockIdx.x * blockDim.x + threadIdx.x) * 4;
    if (i >= e) return;
    int e4 = e & ~3;
    int sv[4], dv[4], cnt4 = 0;
    if (*flag) {
        const long long* sb = (const long long*)ei;
        const long long* db = sb + e;
        if (i < e4 && (e & 1) == 0) {
            const longlong2* sp = (const longlong2*)sb;
            const longlong2* dp = (const longlong2*)db;
            longlong2 s0 = sp[i >> 1], s1 = sp[(i >> 1) + 1];
            longlong2 d0 = dp[i >> 1], d1 = dp[(i >> 1) + 1];
            sv[0]=(int)s0.x; sv[1]=(int)s0.y; sv[2]=(int)s1.x; sv[3]=(int)s1.y;
            dv[0]=(int)d0.x; dv[1]=(int)d0.y; dv[2]=(int)d1.x; dv[3]=(int)d1.y;
            cnt4 = 4;
        } else {
            for (int j = i; j < e && j < i + 4; j++) {
                sv[cnt4] = (int)sb[j]; dv[cnt4] = (int)db[j]; cnt4++;
            }
        }
        if (i == 0) {
            for (int j = e4; j < e; j++) {
                int pos = atomicAdd(&cursor[(int)db[j]], 1);
                adj[pos] = (int)sb[j];
            }
        }
    } else {
        const int* sb = (const int*)ei;
        const int* db = sb + e;
        if (i < e4 && (e & 3) == 0) {
            int4 s4 = ((const int4*)sb)[i >> 2];
            int4 d4 = ((const int4*)db)[i >> 2];
            sv[0]=s4.x; sv[1]=s4.y; sv[2]=s4.z; sv[3]=s4.w;
            dv[0]=d4.x; dv[1]=d4.y; dv[2]=d4.z; dv[3]=d4.w;
            cnt4 = 4;
        } else {
            for (int j = i; j < e && j < i + 4; j++) {
                sv[cnt4] = sb[j]; dv[cnt4] = db[j]; cnt4++;
            }
        }
    }
    #pragma unroll
    for (int j = 0; j < 4; j++) {
        if (j < cnt4) {
            int pos = atomicAdd(&cursor[dv[j]], 1);
            adj[pos] = sv[j];
        }
    }
}

// ---------------------------------------------------------------------------
// Tensor-core GEMM (fp32 A): C = half((A @ W) * rsqrt(cnt[m]+1))
__global__ void __launch_bounds__(256, 1)
k_gemm128t(const float4* __restrict__ A, const float* __restrict__ W,
           const int* __restrict__ cnt, uint4* __restrict__ C, int n)
{
    extern __shared__ __half smh[];
    __half* as = smh;
    __half* bt = smh + 16384;
    const int m0 = blockIdx.x * 128;
    const int t  = threadIdx.x;

    #pragma unroll
    for (int i = 0; i < 8; i++) {
        int id = t + 256 * i;
        int m = id >> 4, c = id & 15;
        float4 v0 = make_float4(0.f,0.f,0.f,0.f), v1 = v0;
        if (m0 + m < n) {
            v0 = A[(size_t)(m0 + m) * 32 + c * 2];
            v1 = A[(size_t)(m0 + m) * 32 + c * 2 + 1];
        }
        __half2 h0 = __float22half2_rn(make_float2(v0.x, v0.y));
        __half2 h1 = __float22half2_rn(make_float2(v0.z, v0.w));
        __half2 h2 = __float22half2_rn(make_float2(v1.x, v1.y));
        __half2 h3 = __float22half2_rn(make_float2(v1.z, v1.w));
        uint4 u = make_uint4(*(unsigned*)&h0, *(unsigned*)&h1,
                             *(unsigned*)&h2, *(unsigned*)&h3);
        *(uint4*)(as + m * 128 + ((c ^ (m & 7)) << 3)) = u;
    }
    #pragma unroll
    for (int i = 0; i < 8; i++) {
        int id = t + 256 * i;
        int ck = id >> 7;
        int nn = id & 127;
        float f[8];
        #pragma unroll
        for (int j = 0; j < 8; j++) f[j] = W[(ck * 8 + j) * 128 + nn];
        __half2 h0 = __float22half2_rn(make_float2(f[0], f[1]));
        __half2 h1 = __float22half2_rn(make_float2(f[2], f[3]));
        __half2 h2 = __float22half2_rn(make_float2(f[4], f[5]));
        __half2 h3 = __float22half2_rn(make_float2(f[6], f[7]));
        uint4 u = make_uint4(*(unsigned*)&h0, *(unsigned*)&h1,
                             *(unsigned*)&h2, *(unsigned*)&h3);
        *(uint4*)(bt + nn * 128 + ((ck ^ (nn & 7)) << 3)) = u;
    }
    __syncthreads();

    const int wid = t >> 5, lane = t & 31;
    const int wm = (wid >> 1) * 32;
    const int wn = (wid & 1) * 64;

    float acc[2][8][4];
    #pragma unroll
    for (int mt = 0; mt < 2; mt++)
        #pragma unroll
        for (int nt = 0; nt < 8; nt++)
            #pragma unroll
            for (int j = 0; j < 4; j++) acc[mt][nt][j] = 0.f;

    const unsigned as_base = (unsigned)__cvta_generic_to_shared(as);
    const unsigned bt_base = (unsigned)__cvta_generic_to_shared(bt);
    const int ra = lane & 15;
    const int ka = lane >> 4;
    const int rbn = ((lane >> 4) << 3) + (lane & 7);
    const int kb  = (lane >> 3) & 1;

    #pragma unroll
    for (int ks = 0; ks < 8; ks++) {
        unsigned a[2][4];
        #pragma unroll
        for (int mt = 0; mt < 2; mt++) {
            int row = wm + mt * 16 + ra;
            int c = ks * 2 + ka;
            unsigned addr = as_base + ((row << 8) + ((c ^ (row & 7)) << 4));
            asm volatile("ldmatrix.sync.aligned.m8n8.x4.shared.b16 {%0,%1,%2,%3}, [%4];"
                : "=r"(a[mt][0]), "=r"(a[mt][1]), "=r"(a[mt][2]), "=r"(a[mt][3])
                : "r"(addr));
        }
        unsigned b[4][4];
        #pragma unroll
        for (int np = 0; np < 4; np++) {
            int rn = wn + np * 16 + rbn;
            int c = ks * 2 + kb;
            unsigned addr = bt_base + ((rn << 8) + ((c ^ (rn & 7)) << 4));
            asm volatile("ldmatrix.sync.aligned.m8n8.x4.shared.b16 {%0,%1,%2,%3}, [%4];"
                : "=r"(b[np][0]), "=r"(b[np][1]), "=r"(b[np][2]), "=r"(b[np][3])
                : "r"(addr));
        }
        #pragma unroll
        for (int mt = 0; mt < 2; mt++)
            #pragma unroll
            for (int nt = 0; nt < 8; nt++) {
                unsigned b0 = b[nt >> 1][(nt & 1) * 2];
                unsigned b1 = b[nt >> 1][(nt & 1) * 2 + 1];
                asm volatile(
                    "mma.sync.aligned.m16n8k16.row.col.f32.f16.f16.f32 "
                    "{%0,%1,%2,%3}, {%4,%5,%6,%7}, {%8,%9}, {%0,%1,%2,%3};"
                    : "+f"(acc[mt][nt][0]), "+f"(acc[mt][nt][1]),
                      "+f"(acc[mt][nt][2]), "+f"(acc[mt][nt][3])
                    : "r"(a[mt][0]), "r"(a[mt][1]), "r"(a[mt][2]), "r"(a[mt][3]),
                      "r"(b0), "r"(b1));
            }
    }

    __half2* C2 = (__half2*)C;
    #pragma unroll
    for (int mt = 0; mt < 2; mt++) {
        int row0 = m0 + wm + mt * 16 + (lane >> 2);
        int row1 = row0 + 8;
        float s0 = (row0 < n) ? rsqrtf((float)(cnt[row0] + 1)) : 0.f;
        float s1 = (row1 < n) ? rsqrtf((float)(cnt[row1] + 1)) : 0.f;
        #pragma unroll
        for (int nt = 0; nt < 8; nt++) {
            int cp = (wn + nt * 8) / 2 + (lane & 3);
            if (row0 < n) {
                __half2 h = __float22half2_rn(
                    make_float2(acc[mt][nt][0] * s0, acc[mt][nt][1] * s0));
                C2[(size_t)row0 * 64 + cp] = h;
            }
            if (row1 < n) {
                __half2 h = __float22half2_rn(
                    make_float2(acc[mt][nt][2] * s1, acc[mt][nt][3] * s1));
                C2[(size_t)row1 * 64 + cp] = h;
            }
        }
    }
}

// Tensor-core GEMM (fp16 A), PDL-ready: W tile converted BEFORE grid-dep sync.
__global__ void __launch_bounds__(256, 1)
k_gemm128th(const uint4* __restrict__ A16, const float* __restrict__ W,
            const int* __restrict__ cnt, uint4* __restrict__ C, int n)
{
    extern __shared__ __half smh[];
    __half* as = smh;
    __half* bt = smh + 16384;
    const int m0 = blockIdx.x * 128;
    const int t  = threadIdx.x;

    // Predecessor-independent prologue: W -> fp16 smem (transposed, swizzled).
    #pragma unroll
    for (int i = 0; i < 8; i++) {
        int id = t + 256 * i;
        int ck = id >> 7;
        int nn = id & 127;
        float f[8];
        #pragma unroll
        for (int j = 0; j < 8; j++) f[j] = W[(ck * 8 + j) * 128 + nn];
        __half2 h0 = __float22half2_rn(make_float2(f[0], f[1]));
        __half2 h1 = __float22half2_rn(make_float2(f[2], f[3]));
        __half2 h2 = __float22half2_rn(make_float2(f[4], f[5]));
        __half2 h3 = __float22half2_rn(make_float2(f[6], f[7]));
        uint4 u = make_uint4(*(unsigned*)&h0, *(unsigned*)&h1,
                             *(unsigned*)&h2, *(unsigned*)&h3);
        *(uint4*)(bt + nn * 128 + ((ck ^ (nn & 7)) << 3)) = u;
    }

    GRID_DEP_SYNC();   // wait for gather-1's B2 writes

    #pragma unroll
    for (int i = 0; i < 8; i++) {
        int id = t + 256 * i;
        int m = id >> 4, c = id & 15;
        uint4 u = make_uint4(0u,0u,0u,0u);
        if (m0 + m < n) u = A16[(size_t)(m0 + m) * 16 + c];
        *(uint4*)(as + m * 128 + ((c ^ (m & 7)) << 3)) = u;
    }
    __syncthreads();

    const int wid = t >> 5, lane = t & 31;
    const int wm = (wid >> 1) * 32;
    const int wn = (wid & 1) * 64;

    float acc[2][8][4];
    #pragma unroll
    for (int mt = 0; mt < 2; mt++)
        #pragma unroll
        for (int nt = 0; nt < 8; nt++)
            #pragma unroll
            for (int j = 0; j < 4; j++) acc[mt][nt][j] = 0.f;

    const unsigned as_base = (unsigned)__cvta_generic_to_shared(as);
    const unsigned bt_base = (unsigned)__cvta_generic_to_shared(bt);
    const int ra = lane & 15;
    const int ka = lane >> 4;
    const int rbn = ((lane >> 4) << 3) + (lane & 7);
    const int kb  = (lane >> 3) & 1;

    #pragma unroll
    for (int ks = 0; ks < 8; ks++) {
        unsigned a[2][4];
        #pragma unroll
        for (int mt = 0; mt < 2; mt++) {
            int row = wm + mt * 16 + ra;
            int c = ks * 2 + ka;
            unsigned addr = as_base + ((row << 8) + ((c ^ (row & 7)) << 4));
            asm volatile("ldmatrix.sync.aligned.m8n8.x4.shared.b16 {%0,%1,%2,%3}, [%4];"
                : "=r"(a[mt][0]), "=r"(a[mt][1]), "=r"(a[mt][2]), "=r"(a[mt][3])
                : "r"(addr));
        }
        unsigned b[4][4];
        #pragma unroll
        for (int np = 0; np < 4; np++) {
            int rn = wn + np * 16 + rbn;
            int c = ks * 2 + kb;
            unsigned addr = bt_base + ((rn << 8) + ((c ^ (rn & 7)) << 4));
            asm volatile("ldmatrix.sync.aligned.m8n8.x4.shared.b16 {%0,%1,%2,%3}, [%4];"
                : "=r"(b[np][0]), "=r"(b[np][1]), "=r"(b[np][2]), "=r"(b[np][3])
                : "r"(addr));
        }
        #pragma unroll
        for (int mt = 0; mt < 2; mt++)
            #pragma unroll
            for (int nt = 0; nt < 8; nt++) {
                unsigned b0 = b[nt >> 1][(nt & 1) * 2];
                unsigned b1 = b[nt >> 1][(nt & 1) * 2 + 1];
                asm volatile(
                    "mma.sync.aligned.m16n8k16.row.col.f32.f16.f16.f32 "
                    "{%0,%1,%2,%3}, {%4,%5,%6,%7}, {%8,%9}, {%0,%1,%2,%3};"
                    : "+f"(acc[mt][nt][0]), "+f"(acc[mt][nt][1]),
                      "+f"(acc[mt][nt][2]), "+f"(acc[mt][nt][3])
                    : "r"(a[mt][0]), "r"(a[mt][1]), "r"(a[mt][2]), "r"(a[mt][3]),
                      "r"(b0), "r"(b1));
            }
    }

    __half2* C2 = (__half2*)C;
    #pragma unroll
    for (int mt = 0; mt < 2; mt++) {
        int row0 = m0 + wm + mt * 16 + (lane >> 2);
        int row1 = row0 + 8;
        float s0 = (row0 < n) ? rsqrtf((float)(cnt[row0] + 1)) : 0.f;
        float s1 = (row1 < n) ? rsqrtf((float)(cnt[row1] + 1)) : 0.f;
        #pragma unroll
        for (int nt = 0; nt < 8; nt++) {
            int cp = (wn + nt * 8) / 2 + (lane & 3);
            if (row0 < n) {
                __half2 h = __float22half2_rn(
                    make_float2(acc[mt][nt][0] * s0, acc[mt][nt][1] * s0));
                C2[(size_t)row0 * 64 + cp] = h;
            }
            if (row1 < n) {
                __half2 h = __float22half2_rn(
                    make_float2(acc[mt][nt][2] * s1, acc[mt][nt][3] * s1));
                C2[(size_t)row1 * 64 + cp] = h;
            }
        }
    }
}

// ---------------------------------------------------------------------------
__device__ __forceinline__ void acc_add8(float4& a, float4& b, uint4 v) {
    float2 f0 = __half22float2(*(__half2*)&v.x);
    float2 f1 = __half22float2(*(__half2*)&v.y);
    float2 f2 = __half22float2(*(__half2*)&v.z);
    float2 f3 = __half22float2(*(__half2*)&v.w);
    a.x += f0.x; a.y += f0.y; a.z += f1.x; a.w += f1.y;
    b.x += f2.x; b.y += f2.y; b.z += f3.x; b.w += f3.y;
}

// Fused aggregation, PDL-ready: rowptr/cnt loads before grid-dep sync.
__global__ void __launch_bounds__(256)
k_gather(const uint4* __restrict__ h4, const int* __restrict__ row_ptr,
         const int* __restrict__ adj, const int* __restrict__ cnt,
         const float* __restrict__ b, uint2* __restrict__ out, int n, int relu)
{
    int w = (blockIdx.x * 256 + threadIdx.x) >> 5;
    int lane = threadIdx.x & 31;
    if (w >= n) return;
    const int half = lane >> 4, cl = lane & 15;
    // Predecessor-independent loads (CSR + bias + degree)
    int beg = __ldg(&row_ptr[w]);
    int end = __ldg(&row_ptr[w + 1]);
    float sc = rsqrtf((float)(__ldg(&cnt[w]) + 1));
    float4 bb = ((const float4*)b)[cl * 2 + half];

    GRID_DEP_SYNC();   // wait for predecessor's h4 writes

    float4 accA = make_float4(0.f,0.f,0.f,0.f);
    float4 accB = make_float4(0.f,0.f,0.f,0.f);
    if (half == 0) acc_add8(accA, accB, h4[(size_t)w * 16 + cl]);   // self-loop

    int i = beg + half;
    for (; i + 2 < end; i += 4) {
        int s0 = __ldg(&adj[i]);
        int s1 = __ldg(&adj[i + 2]);
        uint4 v0 = h4[(size_t)s0 * 16 + cl];
        uint4 v1 = h4[(size_t)s1 * 16 + cl];
        acc_add8(accA, accB, v0);
        acc_add8(accA, accB, v1);
    }
    for (; i < end; i += 2) {
        int s0 = __ldg(&adj[i]);
        acc_add8(accA, accB, h4[(size_t)s0 * 16 + cl]);
    }

    accA.x += __shfl_xor_sync(0xffffffffu, accA.x, 16);
    accA.y += __shfl_xor_sync(0xffffffffu, accA.y, 16);
    accA.z += __shfl_xor_sync(0xffffffffu, accA.z, 16);
    accA.w += __shfl_xor_sync(0xffffffffu, accA.w, 16);
    accB.x += __shfl_xor_sync(0xffffffffu, accB.x, 16);
    accB.y += __shfl_xor_sync(0xffffffffu, accB.y, 16);
    accB.z += __shfl_xor_sync(0xffffffffu, accB.z, 16);
    accB.w += __shfl_xor_sync(0xffffffffu, accB.w, 16);

    float4 acc = (half == 0) ? accA : accB;
    float4 r;
    r.x = acc.x * sc + bb.x;
    r.y = acc.y * sc + bb.y;
    r.z = acc.z * sc + bb.z;
    r.w = acc.w * sc + bb.w;
    if (relu) {
        r.x = fmaxf(r.x, 0.f); r.y = fmaxf(r.y, 0.f);
        r.z = fmaxf(r.z, 0.f); r.w = fmaxf(r.w, 0.f);
    }
    __half2 p0 = __float22half2_rn(make_float2(r.x, r.y));
    __half2 p1 = __float22half2_rn(make_float2(r.z, r.w));
    out[(size_t)w * 32 + cl * 2 + half] = make_uint2(*(unsigned*)&p0, *(unsigned*)&p1);
}

// ---------------------------------------------------------------------------
// Tensor-core head (fp16 H), PDL-ready: Wa/bias smem before grid-dep sync.
__global__ void __launch_bounds__(256, 1)
k_final_tc(const uint4* __restrict__ H16, const float* __restrict__ Wa,
           const float* __restrict__ ba, float* __restrict__ out, int n)
{
    extern __shared__ __half smh[];
    __half* hs = smh;
    __half* wt = smh + 16384;
    float*  bas = (float*)(smh + 32768);
    const int m0 = blockIdx.x * 128;
    const int t  = threadIdx.x;

    // Predecessor-independent prologue: Wa + bias.
    #pragma unroll
    for (int i = 0; i < 8; i++) {
        int id = t + 256 * i;
        int ck = id >> 7;
        int nn = id & 127;
        float f[8];
        #pragma unroll
        for (int j = 0; j < 8; j++)
            f[j] = (nn < 100) ? Wa[(ck * 8 + j) * 100 + nn] : 0.f;
        __half2 h0 = __float22half2_rn(make_float2(f[0], f[1]));
        __half2 h1 = __float22half2_rn(make_float2(f[2], f[3]));
        __half2 h2 = __float22half2_rn(make_float2(f[4], f[5]));
        __half2 h3 = __float22half2_rn(make_float2(f[6], f[7]));
        uint4 u = make_uint4(*(unsigned*)&h0, *(unsigned*)&h1,
                             *(unsigned*)&h2, *(unsigned*)&h3);
        *(uint4*)(wt + nn * 128 + ((ck ^ (nn & 7)) << 3)) = u;
    }
    if (t < 128) bas[t] = (t < 100) ? ba[t] : -1e30f;

    GRID_DEP_SYNC();   // wait for gather-2's B2 writes

    #pragma unroll
    for (int i = 0; i < 8; i++) {
        int id = t + 256 * i;
        int m = id >> 4, c = id & 15;
        uint4 u = make_uint4(0u,0u,0u,0u);
        if (m0 + m < n) u = H16[(size_t)(m0 + m) * 16 + c];
        *(uint4*)(hs + m * 128 + ((c ^ (m & 7)) << 3)) = u;
    }
    __syncthreads();

    const int wid = t >> 5, lane = t & 31;
    const int wm = wid * 16;

    float acc[16][4];
    #pragma unroll
    for (int nt = 0; nt < 16; nt++)
        #pragma unroll
        for (int j = 0; j < 4; j++) acc[nt][j] = 0.f;

    const unsigned hs_base = (unsigned)__cvta_generic_to_shared(hs);
    const unsigned wt_base = (unsigned)__cvta_generic_to_shared(wt);
    const int ra = lane & 15;
    const int ka = lane >> 4;
    const int rbn = ((lane >> 4) << 3) + (lane & 7);
    const int kb  = (lane >> 3) & 1;

    #pragma unroll
    for (int ks = 0; ks < 8; ks++) {
        unsigned a[4];
        {
            int row = wm + ra;
            int c = ks * 2 + ka;
            unsigned addr = hs_base + ((row << 8) + ((c ^ (row & 7)) << 4));
            asm volatile("ldmatrix.sync.aligned.m8n8.x4.shared.b16 {%0,%1,%2,%3}, [%4];"
                : "=r"(a[0]), "=r"(a[1]), "=r"(a[2]), "=r"(a[3]) : "r"(addr));
        }
        #pragma unroll
        for (int np = 0; np < 8; np++) {
            unsigned b[4];
            int rn = np * 16 + rbn;
            int c = ks * 2 + kb;
            unsigned addr = wt_base + ((rn << 8) + ((c ^ (rn & 7)) << 4));
            asm volatile("ldmatrix.sync.aligned.m8n8.x4.shared.b16 {%0,%1,%2,%3}, [%4];"
                : "=r"(b[0]), "=r"(b[1]), "=r"(b[2]), "=r"(b[3]) : "r"(addr));
            #pragma unroll
            for (int half = 0; half < 2; half++) {
                int nt = np * 2 + half;
                asm volatile(
                    "mma.sync.aligned.m16n8k16.row.col.f32.f16.f16.f32 "
                    "{%0,%1,%2,%3}, {%4,%5,%6,%7}, {%8,%9}, {%0,%1,%2,%3};"
                    : "+f"(acc[nt][0]), "+f"(acc[nt][1]),
                      "+f"(acc[nt][2]), "+f"(acc[nt][3])
                    : "r"(a[0]), "r"(a[1]), "r"(a[2]), "r"(a[3]),
                      "r"(b[half * 2]), "r"(b[half * 2 + 1]));
            }
        }
    }

    float v0[32], v1[32];
    float mx0 = -1e30f, mx1 = -1e30f;
    #pragma unroll
    for (int nt = 0; nt < 16; nt++) {
        int c = nt * 8 + (lane & 3) * 2;
        float bb0 = bas[c], bb1 = bas[c + 1];
        v0[nt*2]   = acc[nt][0] + bb0;  v0[nt*2+1] = acc[nt][1] + bb1;
        v1[nt*2]   = acc[nt][2] + bb0;  v1[nt*2+1] = acc[nt][3] + bb1;
        mx0 = fmaxf(mx0, fmaxf(v0[nt*2], v0[nt*2+1]));
        mx1 = fmaxf(mx1, fmaxf(v1[nt*2], v1[nt*2+1]));
    }
    mx0 = fmaxf(mx0, __shfl_xor_sync(0xffffffffu, mx0, 1));
    mx0 = fmaxf(mx0, __shfl_xor_sync(0xffffffffu, mx0, 2));
    mx1 = fmaxf(mx1, __shfl_xor_sync(0xffffffffu, mx1, 1));
    mx1 = fmaxf(mx1, __shfl_xor_sync(0xffffffffu, mx1, 2));
    float sum0 = 0.f, sum1 = 0.f;
    #pragma unroll
    for (int j = 0; j < 32; j++) {
        v0[j] = expf(v0[j] - mx0); sum0 += v0[j];
        v1[j] = expf(v1[j] - mx1); sum1 += v1[j];
    }
    sum0 += __shfl_xor_sync(0xffffffffu, sum0, 1);
    sum0 += __shfl_xor_sync(0xffffffffu, sum0, 2);
    sum1 += __shfl_xor_sync(0xffffffffu, sum1, 1);
    sum1 += __shfl_xor_sync(0xffffffffu, sum1, 2);
    float inv0 = 1.0f / sum0, inv1 = 1.0f / sum1;

    int r0 = m0 + wm + (lane >> 2);
    int r1 = r0 + 8;
    #pragma unroll
    for (int nt = 0; nt < 16; nt++) {
        int c = nt * 8 + (lane & 3) * 2;
        if (c < 100) {
            if (r0 < n)
                *(float2*)(out + (size_t)r0 * 100 + c) =
                    make_float2(v0[nt*2] * inv0, v0[nt*2+1] * inv0);
            if (r1 < n)
                *(float2*)(out + (size_t)r1 * 100 + c) =
                    make_float2(v1[nt*2] * inv1, v1[nt*2+1] * inv1);
        }
    }
}

// ---------------------------------------------------------------------------
extern "C" void kernel_launch(void* const* d_in, const int* in_sizes, int n_in,
                              void* d_out, int out_size)
{
    int ix = 0, ie = 1, iW1 = 2, ib1 = 3, iW2 = 4, ib2 = 5, iWa = 6, iba = 7;
    {
        int jx=-1, je=-1, jW1=-1, jW2=-1, jb1=-1, jb2=-1, jWa=-1, jba=-1;
        for (int i = 0; i < n_in; i++) {
            int s = in_sizes[i];
            if      (s == 6400000) jx = i;
            else if (s == 3200000) je = i;
            else if (s == 16384)   { if (jW1 < 0) jW1 = i; else jW2 = i; }
            else if (s == 128)     { if (jb1 < 0) jb1 = i; else jb2 = i; }
            else if (s == 12800)   jWa = i;
            else if (s == 100)     jba = i;
        }
        if (jx>=0 && je>=0 && jW1>=0 && jW2>=0 && jb1>=0 && jb2>=0 && jWa>=0 && jba>=0) {
            ix=jx; ie=je; iW1=jW1; iW2=jW2; ib1=jb1; ib2=jb2; iWa=jWa; iba=jba;
        }
    }

    const float4* x   = (const float4*)d_in[ix];
    const void*   ei  = d_in[ie];
    const float*  W1  = (const float*)d_in[iW1];
    const float*  b1  = (const float*)d_in[ib1];
    const float*  W2  = (const float*)d_in[iW2];
    const float*  b2  = (const float*)d_in[ib2];
    const float*  Wa  = (const float*)d_in[iWa];
    const float*  ba  = (const float*)d_in[iba];
    float*        out = (float*)d_out;

    const int n = in_sizes[ix] / D;
    const int e = in_sizes[ie] / 2;

    uint4 *H, *B2;
    int *cnt, *rowptr, *cursor, *adj, *blk_agg, *blk_flag, *is64;
    cudaGetSymbolAddress((void**)&H, g_H);
    cudaGetSymbolAddress((void**)&B2, g_B2);
    cudaGetSymbolAddress((void**)&cnt, g_cnt);
    cudaGetSymbolAddress((void**)&rowptr, g_rowptr);
    cudaGetSymbolAddress((void**)&cursor, g_cursor);
    cudaGetSymbolAddress((void**)&adj, g_adj);
    cudaGetSymbolAddress((void**)&blk_agg, g_blk_agg);
    cudaGetSymbolAddress((void**)&blk_flag, g_blk_flag);
    cudaGetSymbolAddress((void**)&is64, g_is64);

    const int SMEM_TC    = 2 * 128 * 128 * 2;
    const int SMEM_FINAL = 2 * 128 * 128 * 2 + 128 * 4;
    cudaFuncSetAttribute(k_gemm128t,  cudaFuncAttributeMaxDynamicSharedMemorySize, SMEM_TC);
    cudaFuncSetAttribute(k_gemm128th, cudaFuncAttributeMaxDynamicSharedMemorySize, SMEM_TC);
    cudaFuncSetAttribute(k_final_tc,  cudaFuncAttributeMaxDynamicSharedMemorySize, SMEM_FINAL);

    const int gemm_blocks = (n + 127) / 128;
    const int nb = (n + 255) / 256;
    const int e4b = ((e + 3) / 4 + 255) / 256;
    const int gb = (n * 32 + 255) / 256;
    const int scan_blocks = (n + SCAN_TILE - 1) / SCAN_TILE;

    cudaStream_t s1 = 0;
    cudaEvent_t evA = 0, evB = 0;
    bool par = (cudaStreamCreateWithFlags(&s1, cudaStreamNonBlocking) == cudaSuccess);
    if (par) par = (cudaEventCreateWithFlags(&evA, cudaEventDisableTiming) == cudaSuccess);
    if (par) par = (cudaEventCreateWithFlags(&evB, cudaEventDisableTiming) == cudaSuccess);

    // PDL launch helper state
    cudaLaunchAttribute pdlAttr[1];
    pdlAttr[0].id = cudaLaunchAttributeProgrammaticStreamSerialization;
    pdlAttr[0].val.programmaticStreamSerializationAllowed = 1;

    // Prefix: fused zero+detect, degree count (stream 0)
    k_init<<<nb, 256>>>((const unsigned int*)ei, is64, cnt, blk_flag, n);
    k_count<<<e4b, 256>>>(ei, is64, cnt, e);

    if (par) {
        cudaEventRecord(evA, 0);
        cudaStreamWaitEvent(s1, evA, 0);
        k_gemm128t<<<gemm_blocks, 256, SMEM_TC, s1>>>(x, W1, cnt, H, n);
        cudaEventRecord(evB, s1);
        k_scan<<<scan_blocks, 256>>>(cnt, rowptr, cursor, blk_agg, blk_flag, n);
        k_fill<<<e4b, 256>>>(ei, is64, cursor, adj, e);
        cudaStreamWaitEvent(0, evB, 0);
    } else {
        k_scan<<<scan_blocks, 256>>>(cnt, rowptr, cursor, blk_agg, blk_flag, n);
        k_fill<<<e4b, 256>>>(ei, is64, cursor, adj, e);
        k_gemm128t<<<gemm_blocks, 256, SMEM_TC>>>(x, W1, cnt, H, n);
    }

    // --- Chain with PDL (fallback to plain launches on failure) ---
    {
        cudaLaunchConfig_t cfg{};
        cfg.blockDim = dim3(256, 1, 1);
        cfg.stream = 0;
        cfg.attrs = pdlAttr;
        cfg.numAttrs = 1;

        // gather 1
        cfg.gridDim = dim3(gb, 1, 1);
        cfg.dynamicSmemBytes = 0;
        if (cudaLaunchKernelEx(&cfg, k_gather, (const uint4*)H, (const int*)rowptr,
                               (const int*)adj, (const int*)cnt, b1,
                               (uint2*)B2, n, 1) != cudaSuccess)
            k_gather<<<gb, 256>>>(H, rowptr, adj, cnt, b1, (uint2*)B2, n, 1);

        // gemm 2
        cfg.gridDim = dim3(gemm_blocks, 1, 1);
        cfg.dynamicSmemBytes = SMEM_TC;
        if (cudaLaunchKernelEx(&cfg, k_gemm128th, (const uint4*)B2, W2,
                               (const int*)cnt, H, n) != cudaSuccess)
            k_gemm128th<<<gemm_blocks, 256, SMEM_TC>>>(B2, W2, cnt, H, n);

        // gather 2
        cfg.gridDim = dim3(gb, 1, 1);
        cfg.dynamicSmemBytes = 0;
        if (cudaLaunchKernelEx(&cfg, k_gather, (const uint4*)H, (const int*)rowptr,
                               (const int*)adj, (const int*)cnt, b2,
                               (uint2*)B2, n, 0) != cudaSuccess)
            k_gather<<<gb, 256>>>(H, rowptr, adj, cnt, b2, (uint2*)B2, n, 0);

        // head + softmax
        cfg.gridDim = dim3(gemm_blocks, 1, 1);
        cfg.dynamicSmemBytes = SMEM_FINAL;
        if (cudaLaunchKernelEx(&cfg, k_final_tc, (const uint4*)B2, Wa, ba,
                               out, n) != cudaSuccess)
            k_final_tc<<<gemm_blocks, 256, SMEM_FINAL>>>(B2, Wa, ba, out, n);
    }
}

// round 17
// speedup vs baseline: 1.0096x; 1.0096x over previous
#include <cuda_runtime.h>
#include <cuda_fp16.h>

// Problem constants
#define D 128
#define NMAX 50000
#define EMAX 1600000
#define SCAN_TILE 1024
#define MAX_BLOCKS 64

// Scratch (uint4 => 16B alignment). Zero-initialized at module load; the tail
// of k_final_tc re-zeroes cnt/blk_flag so every launch starts from zero state.
__device__ uint4  g_H[NMAX * 16];    // pre-scaled linear output, fp16
__device__ uint4  g_B2[NMAX * 16];   // activations, fp16
__device__ int    g_cnt[NMAX];
__device__ int    g_rowptr[NMAX + 1];
__device__ int    g_cursor[NMAX];
__device__ int    g_adj[EMAX];
__device__ int    g_blk_agg[MAX_BLOCKS];
__device__ int    g_blk_flag[MAX_BLOCKS];

// ---------------------------------------------------------------------------
// Per-block edge dtype detection: odd 32-bit words of int64 indices < 50000
// are all zero; for int32 they are random node ids. 2KB read, L2-hot.
__device__ __forceinline__ int detect_is64(const unsigned int* __restrict__ p) {
    __shared__ unsigned int s_det;
    if (threadIdx.x == 0) s_det = 0u;
    __syncthreads();
    unsigned int v = p[threadIdx.x * 2 + 1];   // blockDim.x == 256
    #pragma unroll
    for (int o = 16; o >= 1; o >>= 1) v |= __shfl_xor_sync(0xffffffffu, v, o);
    if ((threadIdx.x & 31) == 0) atomicOr(&s_det, v);
    __syncthreads();
    return s_det == 0u;
}

// Count incoming edges, 4 edges/thread vectorized; dtype detected inline.
__global__ void k_count(const void* __restrict__ ei, int* cnt, int e) {
    int is64 = detect_is64((const unsigned int*)ei);
    int i = (blockIdx.x * blockDim.x + threadIdx.x) * 4;
    if (i >= e) return;
    int e4 = e & ~3;
    if (is64) {
        const long long* base = (const long long*)ei + e;
        if (i < e4 && (e & 1) == 0) {
            const longlong2* p = (const longlong2*)base;
            longlong2 a = p[i >> 1];
            longlong2 b = p[(i >> 1) + 1];
            atomicAdd(&cnt[(int)a.x], 1);
            atomicAdd(&cnt[(int)a.y], 1);
            atomicAdd(&cnt[(int)b.x], 1);
            atomicAdd(&cnt[(int)b.y], 1);
        } else {
            for (int j = i; j < e && j < i + 4; j++)
                atomicAdd(&cnt[(int)base[j]], 1);
        }
        if (i == 0) {
            for (int j = e4; j < e; j++) atomicAdd(&cnt[(int)base[j]], 1);
        }
    } else {
        const int* base = (const int*)ei + e;
        if (i < e4 && (e & 3) == 0) {
            int4 d = ((const int4*)base)[i >> 2];
            atomicAdd(&cnt[d.x], 1);
            atomicAdd(&cnt[d.y], 1);
            atomicAdd(&cnt[d.z], 1);
            atomicAdd(&cnt[d.w], 1);
        } else {
            for (int j = i; j < e && j < i + 4; j++)
                atomicAdd(&cnt[base[j]], 1);
        }
    }
}

// ---------------------------------------------------------------------------
// Single-kernel exclusive scan, parallel decoupled lookback.
__global__ void k_scan(const int* __restrict__ cnt, int* __restrict__ row_ptr,
                       int* __restrict__ cursor, int* __restrict__ blk_agg,
                       int* blk_flag, int n) {
    __shared__ int ws[8];
    __shared__ int s_prev;
    __shared__ int s_agg;
    const int lane = threadIdx.x & 31, wid = threadIdx.x >> 5;
    if (threadIdx.x == 0) s_prev = 0;
    int i0 = blockIdx.x * SCAN_TILE + threadIdx.x * 4;
    int v[4], s = 0;
    #pragma unroll
    for (int j = 0; j < 4; j++) {
        int i = i0 + j;
        v[j] = (i < n) ? cnt[i] : 0;
        s += v[j];
    }
    int x = s;
    #pragma unroll
    for (int o = 1; o < 32; o <<= 1) {
        int y = __shfl_up_sync(0xffffffffu, x, o);
        if (lane >= o) x += y;
    }
    if (lane == 31) ws[wid] = x;
    __syncthreads();

    if (threadIdx.x == 0) {
        int agg = 0;
        #pragma unroll
        for (int j = 0; j < 8; j++) agg += ws[j];
        s_agg = agg;
        blk_agg[blockIdx.x] = agg;
        __threadfence();
        ((volatile int*)blk_flag)[blockIdx.x] = 1;
    }
    if (threadIdx.x < 64) {
        int partial = 0;
        for (int b = threadIdx.x; b < (int)blockIdx.x; b += 64) {
            while (((volatile int*)blk_flag)[b] == 0) { }
            partial += ((volatile int*)blk_agg)[b];
        }
        if (partial) atomicAdd(&s_prev, partial);
    }
    __syncthreads();

    if (threadIdx.x == 0 && blockIdx.x == gridDim.x - 1)
        row_ptr[n] = s_prev + s_agg;

    int warp_off = 0;
    #pragma unroll
    for (int j = 0; j < 7; j++) if (j < wid) warp_off += ws[j];
    int run = s_prev + warp_off + x - s;
    #pragma unroll
    for (int j = 0; j < 4; j++) {
        int i = i0 + j;
        if (i < n) {
            row_ptr[i] = run;
            cursor[i]  = run;
            run += v[j];
        }
    }
}

// Bin edges into CSR, 4 edges/thread vectorized; dtype detected inline.
__global__ void k_fill(const void* __restrict__ ei, int* cursor,
                       int* __restrict__ adj, int e) {
    int is64 = detect_is64((const unsigned int*)ei);
    int i = (blockIdx.x * blockDim.x + threadIdx.x) * 4;
    if (i >= e) return;
    int e4 = e & ~3;
    int sv[4], dv[4], cnt4 = 0;
    if (is64) {
        const long long* sb = (const long long*)ei;
        const long long* db = sb + e;
        if (i < e4 && (e & 1) == 0) {
            const longlong2* sp = (const longlong2*)sb;
            const longlong2* dp = (const longlong2*)db;
            longlong2 s0 = sp[i >> 1], s1 = sp[(i >> 1) + 1];
            longlong2 d0 = dp[i >> 1], d1 = dp[(i >> 1) + 1];
            sv[0]=(int)s0.x; sv[1]=(int)s0.y; sv[2]=(int)s1.x; sv[3]=(int)s1.y;
            dv[0]=(int)d0.x; dv[1]=(int)d0.y; dv[2]=(int)d1.x; dv[3]=(int)d1.y;
            cnt4 = 4;
        } else {
            for (int j = i; j < e && j < i + 4; j++) {
                sv[cnt4] = (int)sb[j]; dv[cnt4] = (int)db[j]; cnt4++;
            }
        }
        if (i == 0) {
            for (int j = e4; j < e; j++) {
                int pos = atomicAdd(&cursor[(int)db[j]], 1);
                adj[pos] = (int)sb[j];
            }
        }
    } else {
        const int* sb = (const int*)ei;
        const int* db = sb + e;
        if (i < e4 && (e & 3) == 0) {
            int4 s4 = ((const int4*)sb)[i >> 2];
            int4 d4 = ((const int4*)db)[i >> 2];
            sv[0]=s4.x; sv[1]=s4.y; sv[2]=s4.z; sv[3]=s4.w;
            dv[0]=d4.x; dv[1]=d4.y; dv[2]=d4.z; dv[3]=d4.w;
            cnt4 = 4;
        } else {
            for (int j = i; j < e && j < i + 4; j++) {
                sv[cnt4] = sb[j]; dv[cnt4] = db[j]; cnt4++;
            }
        }
    }
    #pragma unroll
    for (int j = 0; j < 4; j++) {
        if (j < cnt4) {
            int pos = atomicAdd(&cursor[dv[j]], 1);
            adj[pos] = sv[j];
        }
    }
}

// ---------------------------------------------------------------------------
// Tensor-core GEMM (fp32 A): C = half((A @ W) * rsqrt(cnt[m]+1))
__global__ void __launch_bounds__(256, 1)
k_gemm128t(const float4* __restrict__ A, const float* __restrict__ W,
           const int* __restrict__ cnt, uint4* __restrict__ C, int n)
{
    extern __shared__ __half smh[];
    __half* as = smh;
    __half* bt = smh + 16384;
    const int m0 = blockIdx.x * 128;
    const int t  = threadIdx.x;

    #pragma unroll
    for (int i = 0; i < 8; i++) {
        int id = t + 256 * i;
        int m = id >> 4, c = id & 15;
        float4 v0 = make_float4(0.f,0.f,0.f,0.f), v1 = v0;
        if (m0 + m < n) {
            v0 = A[(size_t)(m0 + m) * 32 + c * 2];
            v1 = A[(size_t)(m0 + m) * 32 + c * 2 + 1];
        }
        __half2 h0 = __float22half2_rn(make_float2(v0.x, v0.y));
        __half2 h1 = __float22half2_rn(make_float2(v0.z, v0.w));
        __half2 h2 = __float22half2_rn(make_float2(v1.x, v1.y));
        __half2 h3 = __float22half2_rn(make_float2(v1.z, v1.w));
        uint4 u = make_uint4(*(unsigned*)&h0, *(unsigned*)&h1,
                             *(unsigned*)&h2, *(unsigned*)&h3);
        *(uint4*)(as + m * 128 + ((c ^ (m & 7)) << 3)) = u;
    }
    #pragma unroll
    for (int i = 0; i < 8; i++) {
        int id = t + 256 * i;
        int ck = id >> 7;
        int nn = id & 127;
        float f[8];
        #pragma unroll
        for (int j = 0; j < 8; j++) f[j] = W[(ck * 8 + j) * 128 + nn];
        __half2 h0 = __float22half2_rn(make_float2(f[0], f[1]));
        __half2 h1 = __float22half2_rn(make_float2(f[2], f[3]));
        __half2 h2 = __float22half2_rn(make_float2(f[4], f[5]));
        __half2 h3 = __float22half2_rn(make_float2(f[6], f[7]));
        uint4 u = make_uint4(*(unsigned*)&h0, *(unsigned*)&h1,
                             *(unsigned*)&h2, *(unsigned*)&h3);
        *(uint4*)(bt + nn * 128 + ((ck ^ (nn & 7)) << 3)) = u;
    }
    __syncthreads();

    const int wid = t >> 5, lane = t & 31;
    const int wm = (wid >> 1) * 32;
    const int wn = (wid & 1) * 64;

    float acc[2][8][4];
    #pragma unroll
    for (int mt = 0; mt < 2; mt++)
        #pragma unroll
        for (int nt = 0; nt < 8; nt++)
            #pragma unroll
            for (int j = 0; j < 4; j++) acc[mt][nt][j] = 0.f;

    const unsigned as_base = (unsigned)__cvta_generic_to_shared(as);
    const unsigned bt_base = (unsigned)__cvta_generic_to_shared(bt);
    const int ra = lane & 15;
    const int ka = lane >> 4;
    const int rbn = ((lane >> 4) << 3) + (lane & 7);
    const int kb  = (lane >> 3) & 1;

    #pragma unroll
    for (int ks = 0; ks < 8; ks++) {
        unsigned a[2][4];
        #pragma unroll
        for (int mt = 0; mt < 2; mt++) {
            int row = wm + mt * 16 + ra;
            int c = ks * 2 + ka;
            unsigned addr = as_base + ((row << 8) + ((c ^ (row & 7)) << 4));
            asm volatile("ldmatrix.sync.aligned.m8n8.x4.shared.b16 {%0,%1,%2,%3}, [%4];"
                : "=r"(a[mt][0]), "=r"(a[mt][1]), "=r"(a[mt][2]), "=r"(a[mt][3])
                : "r"(addr));
        }
        unsigned b[4][4];
        #pragma unroll
        for (int np = 0; np < 4; np++) {
            int rn = wn + np * 16 + rbn;
            int c = ks * 2 + kb;
            unsigned addr = bt_base + ((rn << 8) + ((c ^ (rn & 7)) << 4));
            asm volatile("ldmatrix.sync.aligned.m8n8.x4.shared.b16 {%0,%1,%2,%3}, [%4];"
                : "=r"(b[np][0]), "=r"(b[np][1]), "=r"(b[np][2]), "=r"(b[np][3])
                : "r"(addr));
        }
        #pragma unroll
        for (int mt = 0; mt < 2; mt++)
            #pragma unroll
            for (int nt = 0; nt < 8; nt++) {
                unsigned b0 = b[nt >> 1][(nt & 1) * 2];
                unsigned b1 = b[nt >> 1][(nt & 1) * 2 + 1];
                asm volatile(
                    "mma.sync.aligned.m16n8k16.row.col.f32.f16.f16.f32 "
                    "{%0,%1,%2,%3}, {%4,%5,%6,%7}, {%8,%9}, {%0,%1,%2,%3};"
                    : "+f"(acc[mt][nt][0]), "+f"(acc[mt][nt][1]),
                      "+f"(acc[mt][nt][2]), "+f"(acc[mt][nt][3])
                    : "r"(a[mt][0]), "r"(a[mt][1]), "r"(a[mt][2]), "r"(a[mt][3]),
                      "r"(b0), "r"(b1));
            }
    }

    __half2* C2 = (__half2*)C;
    #pragma unroll
    for (int mt = 0; mt < 2; mt++) {
        int row0 = m0 + wm + mt * 16 + (lane >> 2);
        int row1 = row0 + 8;
        float s0 = (row0 < n) ? rsqrtf((float)(cnt[row0] + 1)) : 0.f;
        float s1 = (row1 < n) ? rsqrtf((float)(cnt[row1] + 1)) : 0.f;
        #pragma unroll
        for (int nt = 0; nt < 8; nt++) {
            int cp = (wn + nt * 8) / 2 + (lane & 3);
            if (row0 < n) {
                __half2 h = __float22half2_rn(
                    make_float2(acc[mt][nt][0] * s0, acc[mt][nt][1] * s0));
                C2[(size_t)row0 * 64 + cp] = h;
            }
            if (row1 < n) {
                __half2 h = __float22half2_rn(
                    make_float2(acc[mt][nt][2] * s1, acc[mt][nt][3] * s1));
                C2[(size_t)row1 * 64 + cp] = h;
            }
        }
    }
}

// Tensor-core GEMM (fp16 A): C = half((A @ W) * rsqrt(cnt[m]+1))
__global__ void __launch_bounds__(256, 1)
k_gemm128th(const uint4* __restrict__ A16, const float* __restrict__ W,
            const int* __restrict__ cnt, uint4* __restrict__ C, int n)
{
    extern __shared__ __half smh[];
    __half* as = smh;
    __half* bt = smh + 16384;
    const int m0 = blockIdx.x * 128;
    const int t  = threadIdx.x;

    #pragma unroll
    for (int i = 0; i < 8; i++) {
        int id = t + 256 * i;
        int m = id >> 4, c = id & 15;
        uint4 u = make_uint4(0u,0u,0u,0u);
        if (m0 + m < n) u = A16[(size_t)(m0 + m) * 16 + c];
        *(uint4*)(as + m * 128 + ((c ^ (m & 7)) << 3)) = u;
    }
    #pragma unroll
    for (int i = 0; i < 8; i++) {
        int id = t + 256 * i;
        int ck = id >> 7;
        int nn = id & 127;
        float f[8];
        #pragma unroll
        for (int j = 0; j < 8; j++) f[j] = W[(ck * 8 + j) * 128 + nn];
        __half2 h0 = __float22half2_rn(make_float2(f[0], f[1]));
        __half2 h1 = __float22half2_rn(make_float2(f[2], f[3]));
        __half2 h2 = __float22half2_rn(make_float2(f[4], f[5]));
        __half2 h3 = __float22half2_rn(make_float2(f[6], f[7]));
        uint4 u = make_uint4(*(unsigned*)&h0, *(unsigned*)&h1,
                             *(unsigned*)&h2, *(unsigned*)&h3);
        *(uint4*)(bt + nn * 128 + ((ck ^ (nn & 7)) << 3)) = u;
    }
    __syncthreads();

    const int wid = t >> 5, lane = t & 31;
    const int wm = (wid >> 1) * 32;
    const int wn = (wid & 1) * 64;

    float acc[2][8][4];
    #pragma unroll
    for (int mt = 0; mt < 2; mt++)
        #pragma unroll
        for (int nt = 0; nt < 8; nt++)
            #pragma unroll
            for (int j = 0; j < 4; j++) acc[mt][nt][j] = 0.f;

    const unsigned as_base = (unsigned)__cvta_generic_to_shared(as);
    const unsigned bt_base = (unsigned)__cvta_generic_to_shared(bt);
    const int ra = lane & 15;
    const int ka = lane >> 4;
    const int rbn = ((lane >> 4) << 3) + (lane & 7);
    const int kb  = (lane >> 3) & 1;

    #pragma unroll
    for (int ks = 0; ks < 8; ks++) {
        unsigned a[2][4];
        #pragma unroll
        for (int mt = 0; mt < 2; mt++) {
            int row = wm + mt * 16 + ra;
            int c = ks * 2 + ka;
            unsigned addr = as_base + ((row << 8) + ((c ^ (row & 7)) << 4));
            asm volatile("ldmatrix.sync.aligned.m8n8.x4.shared.b16 {%0,%1,%2,%3}, [%4];"
                : "=r"(a[mt][0]), "=r"(a[mt][1]), "=r"(a[mt][2]), "=r"(a[mt][3])
                : "r"(addr));
        }
        unsigned b[4][4];
        #pragma unroll
        for (int np = 0; np < 4; np++) {
            int rn = wn + np * 16 + rbn;
            int c = ks * 2 + kb;
            unsigned addr = bt_base + ((rn << 8) + ((c ^ (rn & 7)) << 4));
            asm volatile("ldmatrix.sync.aligned.m8n8.x4.shared.b16 {%0,%1,%2,%3}, [%4];"
                : "=r"(b[np][0]), "=r"(b[np][1]), "=r"(b[np][2]), "=r"(b[np][3])
                : "r"(addr));
        }
        #pragma unroll
        for (int mt = 0; mt < 2; mt++)
            #pragma unroll
            for (int nt = 0; nt < 8; nt++) {
                unsigned b0 = b[nt >> 1][(nt & 1) * 2];
                unsigned b1 = b[nt >> 1][(nt & 1) * 2 + 1];
                asm volatile(
                    "mma.sync.aligned.m16n8k16.row.col.f32.f16.f16.f32 "
                    "{%0,%1,%2,%3}, {%4,%5,%6,%7}, {%8,%9}, {%0,%1,%2,%3};"
                    : "+f"(acc[mt][nt][0]), "+f"(acc[mt][nt][1]),
                      "+f"(acc[mt][nt][2]), "+f"(acc[mt][nt][3])
                    : "r"(a[mt][0]), "r"(a[mt][1]), "r"(a[mt][2]), "r"(a[mt][3]),
                      "r"(b0), "r"(b1));
            }
    }

    __half2* C2 = (__half2*)C;
    #pragma unroll
    for (int mt = 0; mt < 2; mt++) {
        int row0 = m0 + wm + mt * 16 + (lane >> 2);
        int row1 = row0 + 8;
        float s0 = (row0 < n) ? rsqrtf((float)(cnt[row0] + 1)) : 0.f;
        float s1 = (row1 < n) ? rsqrtf((float)(cnt[row1] + 1)) : 0.f;
        #pragma unroll
        for (int nt = 0; nt < 8; nt++) {
            int cp = (wn + nt * 8) / 2 + (lane & 3);
            if (row0 < n) {
                __half2 h = __float22half2_rn(
                    make_float2(acc[mt][nt][0] * s0, acc[mt][nt][1] * s0));
                C2[(size_t)row0 * 64 + cp] = h;
            }
            if (row1 < n) {
                __half2 h = __float22half2_rn(
                    make_float2(acc[mt][nt][2] * s1, acc[mt][nt][3] * s1));
                C2[(size_t)row1 * 64 + cp] = h;
            }
        }
    }
}

// ---------------------------------------------------------------------------
__device__ __forceinline__ void acc_add8(float4& a, float4& b, uint4 v) {
    float2 f0 = __half22float2(*(__half2*)&v.x);
    float2 f1 = __half22float2(*(__half2*)&v.y);
    float2 f2 = __half22float2(*(__half2*)&v.z);
    float2 f3 = __half22float2(*(__half2*)&v.w);
    a.x += f0.x; a.y += f0.y; a.z += f1.x; a.w += f1.y;
    b.x += f2.x; b.y += f2.y; b.z += f3.x; b.w += f3.y;
}

// Fused aggregation: warp/node; half-warps split even/odd edges; 4 loads in
// flight per lane; fp16 in/out.
__global__ void __launch_bounds__(256)
k_gather(const uint4* __restrict__ h4, const int* __restrict__ row_ptr,
         const int* __restrict__ adj, const int* __restrict__ cnt,
         const float* __restrict__ b, uint2* __restrict__ out, int n, int relu)
{
    int w = (blockIdx.x * 256 + threadIdx.x) >> 5;
    int lane = threadIdx.x & 31;
    if (w >= n) return;
    const int half = lane >> 4, cl = lane & 15;
    int beg = __ldg(&row_ptr[w]);
    int end = __ldg(&row_ptr[w + 1]);
    float sc = rsqrtf((float)(__ldg(&cnt[w]) + 1));
    float4 bb = ((const float4*)b)[cl * 2 + half];

    float4 accA = make_float4(0.f,0.f,0.f,0.f);
    float4 accB = make_float4(0.f,0.f,0.f,0.f);
    if (half == 0) acc_add8(accA, accB, h4[(size_t)w * 16 + cl]);   // self-loop

    int i = beg + half;
    for (; i + 6 < end; i += 8) {
        int s0 = __ldg(&adj[i]);
        int s1 = __ldg(&adj[i + 2]);
        int s2 = __ldg(&adj[i + 4]);
        int s3 = __ldg(&adj[i + 6]);
        uint4 v0 = h4[(size_t)s0 * 16 + cl];
        uint4 v1 = h4[(size_t)s1 * 16 + cl];
        uint4 v2 = h4[(size_t)s2 * 16 + cl];
        uint4 v3 = h4[(size_t)s3 * 16 + cl];
        acc_add8(accA, accB, v0);
        acc_add8(accA, accB, v1);
        acc_add8(accA, accB, v2);
        acc_add8(accA, accB, v3);
    }
    for (; i < end; i += 2) {
        int s0 = __ldg(&adj[i]);
        acc_add8(accA, accB, h4[(size_t)s0 * 16 + cl]);
    }

    accA.x += __shfl_xor_sync(0xffffffffu, accA.x, 16);
    accA.y += __shfl_xor_sync(0xffffffffu, accA.y, 16);
    accA.z += __shfl_xor_sync(0xffffffffu, accA.z, 16);
    accA.w += __shfl_xor_sync(0xffffffffu, accA.w, 16);
    accB.x += __shfl_xor_sync(0xffffffffu, accB.x, 16);
    accB.y += __shfl_xor_sync(0xffffffffu, accB.y, 16);
    accB.z += __shfl_xor_sync(0xffffffffu, accB.z, 16);
    accB.w += __shfl_xor_sync(0xffffffffu, accB.w, 16);

    float4 acc = (half == 0) ? accA : accB;
    float4 r;
    r.x = acc.x * sc + bb.x;
    r.y = acc.y * sc + bb.y;
    r.z = acc.z * sc + bb.z;
    r.w = acc.w * sc + bb.w;
    if (relu) {
        r.x = fmaxf(r.x, 0.f); r.y = fmaxf(r.y, 0.f);
        r.z = fmaxf(r.z, 0.f); r.w = fmaxf(r.w, 0.f);
    }
    __half2 p0 = __float22half2_rn(make_float2(r.x, r.y));
    __half2 p1 = __float22half2_rn(make_float2(r.z, r.w));
    out[(size_t)w * 32 + cl * 2 + half] = make_uint2(*(unsigned*)&p0, *(unsigned*)&p1);
}

// ---------------------------------------------------------------------------
// Tensor-core head (fp16 H): out = softmax(H @ Wa + ba).
// Tail: re-zero cnt/blk_flag so the next graph replay starts from zero state.
__global__ void __launch_bounds__(256, 1)
k_final_tc(const uint4* __restrict__ H16, const float* __restrict__ Wa,
           const float* __restrict__ ba, float* __restrict__ out,
           int* __restrict__ cnt_z, int* __restrict__ flag_z, int n)
{
    extern __shared__ __half smh[];
    __half* hs = smh;
    __half* wt = smh + 16384;
    float*  bas = (float*)(smh + 32768);
    const int m0 = blockIdx.x * 128;
    const int t  = threadIdx.x;

    #pragma unroll
    for (int i = 0; i < 8; i++) {
        int id = t + 256 * i;
        int m = id >> 4, c = id & 15;
        uint4 u = make_uint4(0u,0u,0u,0u);
        if (m0 + m < n) u = H16[(size_t)(m0 + m) * 16 + c];
        *(uint4*)(hs + m * 128 + ((c ^ (m & 7)) << 3)) = u;
    }
    #pragma unroll
    for (int i = 0; i < 8; i++) {
        int id = t + 256 * i;
        int ck = id >> 7;
        int nn = id & 127;
        float f[8];
        #pragma unroll
        for (int j = 0; j < 8; j++)
            f[j] = (nn < 100) ? Wa[(ck * 8 + j) * 100 + nn] : 0.f;
        __half2 h0 = __float22half2_rn(make_float2(f[0], f[1]));
        __half2 h1 = __float22half2_rn(make_float2(f[2], f[3]));
        __half2 h2 = __float22half2_rn(make_float2(f[4], f[5]));
        __half2 h3 = __float22half2_rn(make_float2(f[6], f[7]));
        uint4 u = make_uint4(*(unsigned*)&h0, *(unsigned*)&h1,
                             *(unsigned*)&h2, *(unsigned*)&h3);
        *(uint4*)(wt + nn * 128 + ((ck ^ (nn & 7)) << 3)) = u;
    }
    if (t < 128) bas[t] = (t < 100) ? ba[t] : -1e30f;
    __syncthreads();

    // Scratch reset for next invocation (deterministic: every call starts
    // and ends with cnt==0, blk_flag==0).
    {
        int gid = blockIdx.x * 256 + t;
        if (gid < n) cnt_z[gid] = 0;
        if (gid < MAX_BLOCKS) flag_z[gid] = 0;
    }

    const int wid = t >> 5, lane = t & 31;
    const int wm = wid * 16;

    float acc[16][4];
    #pragma unroll
    for (int nt = 0; nt < 16; nt++)
        #pragma unroll
        for (int j = 0; j < 4; j++) acc[nt][j] = 0.f;

    const unsigned hs_base = (unsigned)__cvta_generic_to_shared(hs);
    const unsigned wt_base = (unsigned)__cvta_generic_to_shared(wt);
    const int ra = lane & 15;
    const int ka = lane >> 4;
    const int rbn = ((lane >> 4) << 3) + (lane & 7);
    const int kb  = (lane >> 3) & 1;

    #pragma unroll
    for (int ks = 0; ks < 8; ks++) {
        unsigned a[4];
        {
            int row = wm + ra;
            int c = ks * 2 + ka;
            unsigned addr = hs_base + ((row << 8) + ((c ^ (row & 7)) << 4));
            asm volatile("ldmatrix.sync.aligned.m8n8.x4.shared.b16 {%0,%1,%2,%3}, [%4];"
                : "=r"(a[0]), "=r"(a[1]), "=r"(a[2]), "=r"(a[3]) : "r"(addr));
        }
        #pragma unroll
        for (int np = 0; np < 8; np++) {
            unsigned b[4];
            int rn = np * 16 + rbn;
            int c = ks * 2 + kb;
            unsigned addr = wt_base + ((rn << 8) + ((c ^ (rn & 7)) << 4));
            asm volatile("ldmatrix.sync.aligned.m8n8.x4.shared.b16 {%0,%1,%2,%3}, [%4];"
                : "=r"(b[0]), "=r"(b[1]), "=r"(b[2]), "=r"(b[3]) : "r"(addr));
            #pragma unroll
            for (int half = 0; half < 2; half++) {
                int nt = np * 2 + half;
                asm volatile(
                    "mma.sync.aligned.m16n8k16.row.col.f32.f16.f16.f32 "
                    "{%0,%1,%2,%3}, {%4,%5,%6,%7}, {%8,%9}, {%0,%1,%2,%3};"
                    : "+f"(acc[nt][0]), "+f"(acc[nt][1]),
                      "+f"(acc[nt][2]), "+f"(acc[nt][3])
                    : "r"(a[0]), "r"(a[1]), "r"(a[2]), "r"(a[3]),
                      "r"(b[half * 2]), "r"(b[half * 2 + 1]));
            }
        }
    }

    float v0[32], v1[32];
    float mx0 = -1e30f, mx1 = -1e30f;
    #pragma unroll
    for (int nt = 0; nt < 16; nt++) {
        int c = nt * 8 + (lane & 3) * 2;
        float bb0 = bas[c], bb1 = bas[c + 1];
        v0[nt*2]   = acc[nt][0] + bb0;  v0[nt*2+1] = acc[nt][1] + bb1;
        v1[nt*2]   = acc[nt][2] + bb0;  v1[nt*2+1] = acc[nt][3] + bb1;
        mx0 = fmaxf(mx0, fmaxf(v0[nt*2], v0[nt*2+1]));
        mx1 = fmaxf(mx1, fmaxf(v1[nt*2], v1[nt*2+1]));
    }
    mx0 = fmaxf(mx0, __shfl_xor_sync(0xffffffffu, mx0, 1));
    mx0 = fmaxf(mx0, __shfl_xor_sync(0xffffffffu, mx0, 2));
    mx1 = fmaxf(mx1, __shfl_xor_sync(0xffffffffu, mx1, 1));
    mx1 = fmaxf(mx1, __shfl_xor_sync(0xffffffffu, mx1, 2));
    float sum0 = 0.f, sum1 = 0.f;
    #pragma unroll
    for (int j = 0; j < 32; j++) {
        v0[j] = expf(v0[j] - mx0); sum0 += v0[j];
        v1[j] = expf(v1[j] - mx1); sum1 += v1[j];
    }
    sum0 += __shfl_xor_sync(0xffffffffu, sum0, 1);
    sum0 += __shfl_xor_sync(0xffffffffu, sum0, 2);
    sum1 += __shfl_xor_sync(0xffffffffu, sum1, 1);
    sum1 += __shfl_xor_sync(0xffffffffu, sum1, 2);
    float inv0 = 1.0f / sum0, inv1 = 1.0f / sum1;

    int r0 = m0 + wm + (lane >> 2);
    int r1 = r0 + 8;
    #pragma unroll
    for (int nt = 0; nt < 16; nt++) {
        int c = nt * 8 + (lane & 3) * 2;
        if (c < 100) {
            if (r0 < n)
                *(float2*)(out + (size_t)r0 * 100 + c) =
                    make_float2(v0[nt*2] * inv0, v0[nt*2+1] * inv0);
            if (r1 < n)
                *(float2*)(out + (size_t)r1 * 100 + c) =
                    make_float2(v1[nt*2] * inv1, v1[nt*2+1] * inv1);
        }
    }
}

// ---------------------------------------------------------------------------
extern "C" void kernel_launch(void* const* d_in, const int* in_sizes, int n_in,
                              void* d_out, int out_size)
{
    int ix = 0, ie = 1, iW1 = 2, ib1 = 3, iW2 = 4, ib2 = 5, iWa = 6, iba = 7;
    {
        int jx=-1, je=-1, jW1=-1, jW2=-1, jb1=-1, jb2=-1, jWa=-1, jba=-1;
        for (int i = 0; i < n_in; i++) {
            int s = in_sizes[i];
            if      (s == 6400000) jx = i;
            else if (s == 3200000) je = i;
            else if (s == 16384)   { if (jW1 < 0) jW1 = i; else jW2 = i; }
            else if (s == 128)     { if (jb1 < 0) jb1 = i; else jb2 = i; }
            else if (s == 12800)   jWa = i;
            else if (s == 100)     jba = i;
        }
        if (jx>=0 && je>=0 && jW1>=0 && jW2>=0 && jb1>=0 && jb2>=0 && jWa>=0 && jba>=0) {
            ix=jx; ie=je; iW1=jW1; iW2=jW2; ib1=jb1; ib2=jb2; iWa=jWa; iba=jba;
        }
    }

    const float4* x   = (const float4*)d_in[ix];
    const void*   ei  = d_in[ie];
    const float*  W1  = (const float*)d_in[iW1];
    const float*  b1  = (const float*)d_in[ib1];
    const float*  W2  = (const float*)d_in[iW2];
    const float*  b2  = (const float*)d_in[ib2];
    const float*  Wa  = (const float*)d_in[iWa];
    const float*  ba  = (const float*)d_in[iba];
    float*        out = (float*)d_out;

    const int n = in_sizes[ix] / D;
    const int e = in_sizes[ie] / 2;

    uint4 *H, *B2;
    int *cnt, *rowptr, *cursor, *adj, *blk_agg, *blk_flag;
    cudaGetSymbolAddress((void**)&H, g_H);
    cudaGetSymbolAddress((void**)&B2, g_B2);
    cudaGetSymbolAddress((void**)&cnt, g_cnt);
    cudaGetSymbolAddress((void**)&rowptr, g_rowptr);
    cudaGetSymbolAddress((void**)&cursor, g_cursor);
    cudaGetSymbolAddress((void**)&adj, g_adj);
    cudaGetSymbolAddress((void**)&blk_agg, g_blk_agg);
    cudaGetSymbolAddress((void**)&blk_flag, g_blk_flag);

    const int SMEM_TC    = 2 * 128 * 128 * 2;
    const int SMEM_FINAL = 2 * 128 * 128 * 2 + 128 * 4;
    cudaFuncSetAttribute(k_gemm128t,  cudaFuncAttributeMaxDynamicSharedMemorySize, SMEM_TC);
    cudaFuncSetAttribute(k_gemm128th, cudaFuncAttributeMaxDynamicSharedMemorySize, SMEM_TC);
    cudaFuncSetAttribute(k_final_tc,  cudaFuncAttributeMaxDynamicSharedMemorySize, SMEM_FINAL);

    const int gemm_blocks = (n + 127) / 128;
    const int e4b = ((e + 3) / 4 + 255) / 256;
    const int gb = (n * 32 + 255) / 256;
    const int scan_blocks = (n + SCAN_TILE - 1) / SCAN_TILE;

    cudaStream_t s1 = 0;
    cudaEvent_t evA = 0, evB = 0;
    bool par = (cudaStreamCreateWithFlags(&s1, cudaStreamNonBlocking) == cudaSuccess);
    if (par) par = (cudaEventCreateWithFlags(&evA, cudaEventDisableTiming) == cudaSuccess);
    if (par) par = (cudaEventCreateWithFlags(&evB, cudaEventDisableTiming) == cudaSuccess);

    // Prefix: degree count (cnt is guaranteed zero at entry)
    k_count<<<e4b, 256>>>(ei, cnt, e);

    if (par) {
        cudaEventRecord(evA, 0);
        cudaStreamWaitEvent(s1, evA, 0);
        k_gemm128t<<<gemm_blocks, 256, SMEM_TC, s1>>>(x, W1, cnt, H, n);
        cudaEventRecord(evB, s1);
        k_scan<<<scan_blocks, 256>>>(cnt, rowptr, cursor, blk_agg, blk_flag, n);
        k_fill<<<e4b, 256>>>(ei, cursor, adj, e);
        cudaStreamWaitEvent(0, evB, 0);
    } else {
        k_scan<<<scan_blocks, 256>>>(cnt, rowptr, cursor, blk_agg, blk_flag, n);
        k_fill<<<e4b, 256>>>(ei, cursor, adj, e);
        k_gemm128t<<<gemm_blocks, 256, SMEM_TC>>>(x, W1, cnt, H, n);
    }

    // layer 1 aggregation (fp16 out)
    k_gather<<<gb, 256>>>(H, rowptr, adj, cnt, b1, (uint2*)B2, n, 1);

    // layer 2 (fp16 in/out)
    k_gemm128th<<<gemm_blocks, 256, SMEM_TC>>>(B2, W2, cnt, H, n);
    k_gather<<<gb, 256>>>(H, rowptr, adj, cnt, b2, (uint2*)B2, n, 0);

    // head + softmax (fp16 in); tail re-zeroes cnt/blk_flag for next replay
    k_final_tc<<<gemm_blocks, 256, SMEM_FINAL>>>(B2, Wa, ba, out, cnt, blk_flag, n);
}